// round 5
// baseline (speedup 1.0000x reference)
#include <cuda_runtime.h>
#include <math.h>

#define LLEN 8192
#define BATCH 256
#define TL 1024
#define EPSB 1e-5f
#define XROW 1140
#define FROW 1088

// ---------------- device scratch ----------------
__device__ float g_gram[BATCH * 256];
__device__ float g_Weff[BATCH * 256];

// ---------------------------------------------------------------------------
// Kernel 0: zero the gram accumulator
// ---------------------------------------------------------------------------
__global__ void zero_gram_kernel() {
    g_gram[blockIdx.x * 256 + threadIdx.x] = 0.f;
}

// ---------------------------------------------------------------------------
// Kernel 1: gram of c0, register-only (no LDS in hot loop).
// Grid (8, BATCH). Warp w: row-group r=(w&3)*4, position-half h=(w>>2).
// Each lane: compute c0[16] in regs, accumulate 4x16 products.
// ---------------------------------------------------------------------------
__global__ __launch_bounds__(256) void gram_kernel(
    const float* __restrict__ x,
    const float* __restrict__ wc1, const float* __restrict__ g1,
    const float* __restrict__ bt1, const float* __restrict__ m1,
    const float* __restrict__ v1)
{
    __shared__ float u1s[64];
    __shared__ float sh1s[16];

    const int b = blockIdx.y;
    const int chunk = blockIdx.x;
    const int t = threadIdx.x;
    const int w = t >> 5;
    const int lane = t & 31;
    const int r = (w & 3) * 4;
    const int h = w >> 2;

    if (t < 16) {
        float inv1 = g1[t] * rsqrtf(v1[t] + EPSB);
        sh1s[t] = bt1[t] - m1[t] * inv1;
        #pragma unroll
        for (int i = 0; i < 4; i++) u1s[t * 4 + i] = inv1 * wc1[t * 4 + i];
    }
    __syncthreads();

    float uw[64], sh[16];
    #pragma unroll
    for (int i = 0; i < 64; i++) uw[i] = u1s[i];
    #pragma unroll
    for (int i = 0; i < 16; i++) sh[i] = sh1s[i];

    float acc[4][16];
    #pragma unroll
    for (int j = 0; j < 4; j++)
        #pragma unroll
        for (int dd = 0; dd < 16; dd++) acc[j][dd] = 0.f;

    const int pbase = chunk * 1024 + h * 512 + lane;
    for (int g = 0; g < 16; g++) {
        int p = pbase + g * 32;
        float x0 = x[(b * 4 + 0) * LLEN + p];
        float x1 = x[(b * 4 + 1) * LLEN + p];
        float x2 = x[(b * 4 + 2) * LLEN + p];
        float x3 = x[(b * 4 + 3) * LLEN + p];
        float c0[16];
        #pragma unroll
        for (int c = 0; c < 16; c++) {
            float v = sh[c] + uw[c * 4 + 0] * x0 + uw[c * 4 + 1] * x1
                            + uw[c * 4 + 2] * x2 + uw[c * 4 + 3] * x3;
            c0[c] = fmaxf(v, 0.f);
        }
        #pragma unroll
        for (int j = 0; j < 4; j++) {
            float rv = c0[r + j];
            #pragma unroll
            for (int dd = 0; dd < 16; dd++) acc[j][dd] += rv * c0[dd];
        }
    }

    // lane reduction (butterfly) then lane0 atomics
    #pragma unroll
    for (int j = 0; j < 4; j++)
        #pragma unroll
        for (int dd = 0; dd < 16; dd++) {
            float v = acc[j][dd];
            #pragma unroll
            for (int s = 16; s > 0; s >>= 1)
                v += __shfl_xor_sync(0xffffffffu, v, s);
            acc[j][dd] = v;
        }
    if (lane == 0) {
        #pragma unroll
        for (int j = 0; j < 4; j++)
            #pragma unroll
            for (int dd = 0; dd < 16; dd++)
                atomicAdd(&g_gram[b * 256 + (r + j) * 16 + dd], acc[j][dd]);
    }
}

// ---------------------------------------------------------------------------
// Kernel 2: softmax + fold into W_eff
// ---------------------------------------------------------------------------
__global__ __launch_bounds__(256) void fold_kernel(
    const float* __restrict__ beta_cam,
    const float* __restrict__ wc2, const float* __restrict__ g2,
    const float* __restrict__ v2)
{
    __shared__ float gsm[256];
    __shared__ float asmem[256];
    const int b = blockIdx.x;
    const int t = threadIdx.x;

    gsm[t] = g_gram[b * 256 + t];
    __syncthreads();

    if (t < 16) {
        float rmin = 1e30f;
        #pragma unroll
        for (int d = 0; d < 16; d++) rmin = fminf(rmin, gsm[t * 16 + d]);
        float e[16];
        float s = 0.f;
        #pragma unroll
        for (int d = 0; d < 16; d++) { e[d] = expf(rmin - gsm[t * 16 + d]); s += e[d]; }
        float invs = 1.f / s;
        #pragma unroll
        for (int d = 0; d < 16; d++) asmem[t * 16 + d] = e[d] * invs;
    }
    __syncthreads();

    const int cg = t >> 4;
    const int dg = t & 15;
    float inv2c = g2[cg] * rsqrtf(v2[cg] + EPSB);
    float beta = beta_cam[0];
    float s = 0.f;
    #pragma unroll
    for (int e = 0; e < 16; e++) s += wc2[cg * 16 + e] * asmem[e * 16 + dg];
    g_Weff[b * 256 + t] = inv2c * (beta * s + wc2[cg * 16 + dg]);
}

// ---------------------------------------------------------------------------
// Kernel 3: fused ConvFusion + attention epilogue.
// TL=1024, 256 threads, 4 contiguous positions per thread.
// f0s stored XOR-swizzled on 16B units for conflict-free float4 window loads.
// SMEM layout (floats):
//   xs    [0, 4560)       4 x 1140
//   f0s   [4560, 13264)   8 x 1088 (swizzled)
//   w00s  [13264, 14288)
//   w01t  [14288, 15312)  [d][k][c]
//   w02t  [15312, 16336)  [d][k][c]
//   weffs [16336, 16592)
//   u1s   [16592, 16656)
//   sh1s  [16656,16672) sh2s [16672,16688)
//   b00s  [16688,16696) b01s [16696,16704) b02s [16704,16712)
// total 16712 floats = 66848 B
// ---------------------------------------------------------------------------
#define SMEM_FLOATS 16712

__global__ __launch_bounds__(256, 2) void main_kernel(
    const float* __restrict__ x,
    const float* __restrict__ w00, const float* __restrict__ b00,
    const float* __restrict__ w01, const float* __restrict__ b01,
    const float* __restrict__ w02, const float* __restrict__ b02,
    const float* __restrict__ wc1, const float* __restrict__ g1,
    const float* __restrict__ bt1, const float* __restrict__ m1,
    const float* __restrict__ v1,
    const float* __restrict__ g2, const float* __restrict__ bt2,
    const float* __restrict__ m2, const float* __restrict__ v2,
    float* __restrict__ out)
{
    extern __shared__ float sm[];
    float* xs    = sm;
    float* f0s   = sm + 4560;
    float* w00s  = sm + 13264;
    float* w01t  = sm + 14288;
    float* w02t  = sm + 15312;
    float* weffs = sm + 16336;
    float* u1s   = sm + 16592;
    float* sh1s  = sm + 16656;
    float* sh2s  = sm + 16672;
    float* b00s  = sm + 16688;
    float* b01s  = sm + 16696;
    float* b02s  = sm + 16704;

    const int t = threadIdx.x;
    const int l0 = blockIdx.x * TL;
    const int b = blockIdx.y;

    // ---- phase A: weights ----
    for (int i = t; i < 1024; i += 256) {
        w00s[i] = w00[i];
        int d = i >> 7, k = (i >> 3) & 15, c = i & 7;
        w01t[i] = w01[(c * 8 + d) * 16 + k];
        w02t[i] = w02[(c * 8 + d) * 16 + k];
    }
    if (t < 64) {
        int c = t >> 2;
        float inv1 = g1[c] * rsqrtf(v1[c] + EPSB);
        u1s[t] = inv1 * wc1[t];
    }
    if (t < 16) {
        float inv1 = g1[t] * rsqrtf(v1[t] + EPSB);
        sh1s[t] = bt1[t] - m1[t] * inv1;
        float inv2 = g2[t] * rsqrtf(v2[t] + EPSB);
        sh2s[t] = bt2[t] - m2[t] * inv2;
    }
    weffs[t] = g_Weff[b * 256 + t];
    if (t < 8) { b00s[t] = b00[t]; b01s[t] = b01[t]; b02s[t] = b02[t]; }

    // ---- phase B: x tile with halo ----
    for (int idx = t; idx < 4 * XROW; idx += 256) {
        int i = idx / XROW, o = idx - i * XROW;
        int g = l0 - 32 + o;
        xs[idx] = (g >= 0 && g < LLEN) ? x[(b * 4 + i) * LLEN + g] : 0.f;
    }
    __syncthreads();

    // ---- phase C: fea0 into swizzled f0s. warp=channel d, 2 passes x 17 pos ----
    {
        const int d = t >> 5;
        const int lane = t & 31;
        const float bv = b00s[d];
        #pragma unroll
        for (int pass = 0; pass < 2; pass++) {
            const int jj0 = pass * 544 + lane * 17;
            float acc[17];
            #pragma unroll
            for (int p = 0; p < 17; p++) acc[p] = bv;
            #pragma unroll
            for (int i = 0; i < 4; i++) {
                float xw[48];
                const float* xrow = xs + i * XROW + jj0 + 2;
                #pragma unroll
                for (int m = 0; m < 48; m++) xw[m] = xrow[m];
                float wreg[32];
                const float4* wr4 = (const float4*)(w00s + (d * 4 + i) * 32);
                #pragma unroll
                for (int q = 0; q < 8; q++) {
                    float4 wv = wr4[q];
                    wreg[4 * q] = wv.x; wreg[4 * q + 1] = wv.y;
                    wreg[4 * q + 2] = wv.z; wreg[4 * q + 3] = wv.w;
                }
                #pragma unroll
                for (int k = 0; k < 32; k++) {
                    float wv = wreg[k];
                    #pragma unroll
                    for (int p = 0; p < 17; p++) acc[p] += wv * xw[p + k];
                }
            }
            #pragma unroll
            for (int p = 0; p < 17; p++) {
                int jj = jj0 + p;
                int j = l0 - 14 + jj;
                float val = (j >= 0 && j <= LLEN) ? acc[p] : 0.f;
                int u = jj >> 2;
                int su = u ^ ((u >> 3) & 7);
                f0s[d * FROW + su * 4 + (jj & 3)] = val;
            }
        }
    }
    __syncthreads();

    // ---- phase D: fea1/fea2, scalar, 4 positions per thread ----
    float acc1[4][8], acc2[4][8];
    #pragma unroll
    for (int c = 0; c < 8; c++) {
        float bA = b01s[c], bB = b02s[c];
        #pragma unroll
        for (int p = 0; p < 4; p++) { acc1[p][c] = bA; acc2[p][c] = bB; }
    }

    #pragma unroll 1
    for (int d = 0; d < 8; d++) {
        float win[36];
        #pragma unroll
        for (int q = 0; q < 9; q++) {
            int u = t + q;
            int su = u ^ ((u >> 3) & 7);
            float4 v = *(const float4*)(f0s + d * FROW + su * 4);
            win[4 * q] = v.x; win[4 * q + 1] = v.y;
            win[4 * q + 2] = v.z; win[4 * q + 3] = v.w;
        }
        const float4* w1r = (const float4*)(w01t + d * 128);
        const float4* w2r = (const float4*)(w02t + d * 128);
        #pragma unroll
        for (int k = 0; k < 16; k++) {
            float4 a0 = w1r[2 * k], a1 = w1r[2 * k + 1];
            float4 e0 = w2r[2 * k], e1 = w2r[2 * k + 1];
            float wA[8] = {a0.x, a0.y, a0.z, a0.w, a1.x, a1.y, a1.z, a1.w};
            float wB[8] = {e0.x, e0.y, e0.z, e0.w, e1.x, e1.y, e1.z, e1.w};
            #pragma unroll
            for (int p = 0; p < 4; p++) {
                float fA = win[7 + k + p];
                float fB = win[2 * k + p];
                #pragma unroll
                for (int c = 0; c < 8; c++) {
                    acc1[p][c] += wA[c] * fA;
                    acc2[p][c] += wB[c] * fB;
                }
            }
        }
    }

    // ---- epilogue: c0 via LDG, folded attention, store ----
    float xgf[4][4];
    #pragma unroll
    for (int i = 0; i < 4; i++) {
        float4 v = *(const float4*)(x + (b * 4 + i) * LLEN + l0 + 4 * t);
        xgf[i][0] = v.x; xgf[i][1] = v.y; xgf[i][2] = v.z; xgf[i][3] = v.w;
    }

    const int lbase = l0 + 4 * t;
    #pragma unroll
    for (int pp = 0; pp < 2; pp++) {
        float c0v[2][16];
        #pragma unroll
        for (int p2 = 0; p2 < 2; p2++) {
            int p = pp * 2 + p2;
            float x0 = xgf[0][p], x1 = xgf[1][p], x2 = xgf[2][p], x3 = xgf[3][p];
            #pragma unroll
            for (int c = 0; c < 16; c++) {
                float4 u = *(const float4*)(u1s + c * 4);
                float v = sh1s[c] + u.x * x0 + u.y * x1 + u.z * x2 + u.w * x3;
                c0v[p2][c] = fmaxf(v, 0.f);
            }
        }
        const int l = lbase + 2 * pp;
        #pragma unroll
        for (int c = 0; c < 16; c++) {
            float s0 = sh2s[c], s1 = sh2s[c];
            #pragma unroll
            for (int dq = 0; dq < 16; dq += 4) {
                float4 wv = *(const float4*)(weffs + c * 16 + dq);
                s0 += wv.x * c0v[0][dq] + wv.y * c0v[0][dq + 1]
                    + wv.z * c0v[0][dq + 2] + wv.w * c0v[0][dq + 3];
                s1 += wv.x * c0v[1][dq] + wv.y * c0v[1][dq + 1]
                    + wv.z * c0v[1][dq + 2] + wv.w * c0v[1][dq + 3];
            }
            float f0v, f1v;
            if (c < 8) {
                f0v = acc1[2 * pp][c];
                f1v = acc1[2 * pp + 1][c];
            } else {
                f0v = acc2[2 * pp][c - 8];
                f1v = acc2[2 * pp + 1][c - 8];
                if (l == 0 || l >= LLEN - 2) f0v = 0.f;
                if (l + 1 >= LLEN - 2) f1v = 0.f;
            }
            *(float2*)(out + (b * 16 + c) * LLEN + l) =
                make_float2(f0v + fmaxf(s0, 0.f), f1v + fmaxf(s1, 0.f));
        }
    }
}

// ---------------------------------------------------------------------------
extern "C" void kernel_launch(void* const* d_in, const int* in_sizes, int n_in,
                              void* d_out, int out_size)
{
    const float* x        = (const float*)d_in[0];
    const float* w00      = (const float*)d_in[1];
    const float* b00      = (const float*)d_in[2];
    const float* w01      = (const float*)d_in[3];
    const float* b01      = (const float*)d_in[4];
    const float* w02      = (const float*)d_in[5];
    const float* b02      = (const float*)d_in[6];
    const float* wc1      = (const float*)d_in[7];
    const float* g1       = (const float*)d_in[8];
    const float* bt1      = (const float*)d_in[9];
    const float* m1       = (const float*)d_in[10];
    const float* v1       = (const float*)d_in[11];
    const float* beta_cam = (const float*)d_in[12];
    const float* wc2      = (const float*)d_in[13];
    const float* g2       = (const float*)d_in[14];
    const float* bt2      = (const float*)d_in[15];
    const float* m2       = (const float*)d_in[16];
    const float* v2       = (const float*)d_in[17];
    float* out = (float*)d_out;

    // Unconditional and idempotent: no static guards (harness rule), not a
    // stream op so it does not become a graph node during capture.
    cudaFuncSetAttribute(main_kernel,
                         cudaFuncAttributeMaxDynamicSharedMemorySize,
                         SMEM_FLOATS * 4);

    zero_gram_kernel<<<256, 256>>>();
    dim3 ggrid(8, BATCH);
    gram_kernel<<<ggrid, 256>>>(x, wc1, g1, bt1, m1, v1);
    fold_kernel<<<BATCH, 256>>>(beta_cam, wc2, g2, v2);
    dim3 grid(LLEN / TL, BATCH);
    main_kernel<<<grid, 256, SMEM_FLOATS * 4>>>(
        x, w00, b00, w01, b01, w02, b02,
        wc1, g1, bt1, m1, v1, g2, bt2, m2, v2, out);
}

// round 6
// speedup vs baseline: 1.4758x; 1.4758x over previous
#include <cuda_runtime.h>
#include <math.h>

#define LLEN 8192
#define BATCH 256
#define TL 1024
#define EPSB 1e-5f
#define XROW 1140
#define FROW 1088
#define NCHUNK 8

// ---------------- constant weights (copied D2D each launch) ----------------
__constant__ float cw00[1024];   // [d][i][k] as input layout w00[8][4][32]
__constant__ float cw01[1024];   // input layout [cout][cin][16]
__constant__ float cw02[1024];   // input layout [cout][cin][16]
__constant__ float cb00[8];
__constant__ float cb01[8];
__constant__ float cb02[8];

// ---------------- device scratch ----------------
__device__ float g_gpart[NCHUNK * BATCH * 256];
__device__ float g_Weff[BATCH * 256];

// ---------------------------------------------------------------------------
// Kernel 1: partial gram of c0, 2x2 register tiling, non-atomic partials.
// Grid (NCHUNK, BATCH), 256 threads. Thread: rp=t>>5, cp=(t>>2)&7, ps=t&3.
// ---------------------------------------------------------------------------
__global__ __launch_bounds__(256) void gram_kernel(
    const float* __restrict__ x,
    const float* __restrict__ wc1, const float* __restrict__ g1,
    const float* __restrict__ bt1, const float* __restrict__ m1,
    const float* __restrict__ v1)
{
    __shared__ float c0s[16 * 260];
    __shared__ float u1s[64];
    __shared__ float sh1s[16];

    const int b = blockIdx.y;
    const int chunk = blockIdx.x;
    const int t = threadIdx.x;
    const int rp = t >> 5;
    const int cp = (t >> 2) & 7;
    const int ps = t & 3;

    if (t < 16) {
        float inv1 = g1[t] * rsqrtf(v1[t] + EPSB);
        sh1s[t] = bt1[t] - m1[t] * inv1;
        #pragma unroll
        for (int i = 0; i < 4; i++) u1s[t * 4 + i] = inv1 * wc1[t * 4 + i];
    }
    __syncthreads();

    float uw[64], sh[16];
    #pragma unroll
    for (int i = 0; i < 64; i++) uw[i] = u1s[i];
    #pragma unroll
    for (int i = 0; i < 16; i++) sh[i] = sh1s[i];

    float a00 = 0.f, a01 = 0.f, a10 = 0.f, a11 = 0.f;

    for (int ch = 0; ch < 4; ch++) {
        int p = (chunk * 4 + ch) * 256 + t;
        float xv0 = x[(b * 4 + 0) * LLEN + p];
        float xv1 = x[(b * 4 + 1) * LLEN + p];
        float xv2 = x[(b * 4 + 2) * LLEN + p];
        float xv3 = x[(b * 4 + 3) * LLEN + p];
        __syncthreads();
        #pragma unroll
        for (int c = 0; c < 16; c++) {
            float v = sh[c] + uw[c * 4 + 0] * xv0 + uw[c * 4 + 1] * xv1
                            + uw[c * 4 + 2] * xv2 + uw[c * 4 + 3] * xv3;
            c0s[c * 260 + t] = fmaxf(v, 0.f);
        }
        __syncthreads();
        const float4* r0 = (const float4*)(c0s + (2 * rp) * 260);
        const float4* r1 = (const float4*)(c0s + (2 * rp + 1) * 260);
        const float4* q0 = (const float4*)(c0s + (2 * cp) * 260);
        const float4* q1 = (const float4*)(c0s + (2 * cp + 1) * 260);
        #pragma unroll
        for (int m = 0; m < 16; m++) {
            int j = ps + 4 * m;
            float4 va0 = r0[j], va1 = r1[j];
            float4 vb0 = q0[j], vb1 = q1[j];
            a00 += va0.x * vb0.x + va0.y * vb0.y + va0.z * vb0.z + va0.w * vb0.w;
            a01 += va0.x * vb1.x + va0.y * vb1.y + va0.z * vb1.z + va0.w * vb1.w;
            a10 += va1.x * vb0.x + va1.y * vb0.y + va1.z * vb0.z + va1.w * vb0.w;
            a11 += va1.x * vb1.x + va1.y * vb1.y + va1.z * vb1.z + va1.w * vb1.w;
        }
    }

    // sum over ps (lanes xor 1, 2)
    a00 += __shfl_xor_sync(0xffffffffu, a00, 1);
    a00 += __shfl_xor_sync(0xffffffffu, a00, 2);
    a01 += __shfl_xor_sync(0xffffffffu, a01, 1);
    a01 += __shfl_xor_sync(0xffffffffu, a01, 2);
    a10 += __shfl_xor_sync(0xffffffffu, a10, 1);
    a10 += __shfl_xor_sync(0xffffffffu, a10, 2);
    a11 += __shfl_xor_sync(0xffffffffu, a11, 1);
    a11 += __shfl_xor_sync(0xffffffffu, a11, 2);

    if (ps == 0) {
        float* dst = g_gpart + (chunk * BATCH + b) * 256;
        dst[(2 * rp) * 16 + 2 * cp]         = a00;
        dst[(2 * rp) * 16 + 2 * cp + 1]     = a01;
        dst[(2 * rp + 1) * 16 + 2 * cp]     = a10;
        dst[(2 * rp + 1) * 16 + 2 * cp + 1] = a11;
    }
}

// ---------------------------------------------------------------------------
// Kernel 2: sum partials, softmax + fold into W_eff
// ---------------------------------------------------------------------------
__global__ __launch_bounds__(256) void fold_kernel(
    const float* __restrict__ beta_cam,
    const float* __restrict__ wc2, const float* __restrict__ g2,
    const float* __restrict__ v2)
{
    __shared__ float gsm[256];
    __shared__ float asmem[256];
    const int b = blockIdx.x;
    const int t = threadIdx.x;

    float s = 0.f;
    #pragma unroll
    for (int ch = 0; ch < NCHUNK; ch++)
        s += g_gpart[(ch * BATCH + b) * 256 + t];
    gsm[t] = s;
    __syncthreads();

    if (t < 16) {
        float rmin = 1e30f;
        #pragma unroll
        for (int d = 0; d < 16; d++) rmin = fminf(rmin, gsm[t * 16 + d]);
        float e[16];
        float ssum = 0.f;
        #pragma unroll
        for (int d = 0; d < 16; d++) { e[d] = expf(rmin - gsm[t * 16 + d]); ssum += e[d]; }
        float invs = 1.f / ssum;
        #pragma unroll
        for (int d = 0; d < 16; d++) asmem[t * 16 + d] = e[d] * invs;
    }
    __syncthreads();

    const int cg = t >> 4;
    const int dg = t & 15;
    float inv2c = g2[cg] * rsqrtf(v2[cg] + EPSB);
    float beta = beta_cam[0];
    float acc = 0.f;
    #pragma unroll
    for (int e = 0; e < 16; e++) acc += wc2[cg * 16 + e] * asmem[e * 16 + dg];
    g_Weff[b * 256 + t] = inv2c * (beta * acc + wc2[cg * 16 + dg]);
}

// ---------------------------------------------------------------------------
// Kernel 3: fused ConvFusion + attention epilogue.
// TL=1024, 256 threads, 4 contiguous positions/thread, weights in __constant__.
// Phase D split (fea1 -> epi ch0-7, fea2 -> epi ch8-15) to bound registers.
// SMEM (floats): xs [0,4560) | f0s [4560,13264) swizzled | weffs [13264,13520)
//                u1s [13520,13584) | sh1s [13584,13600) | sh2s [13600,13616)
// total 13616 floats = 54464 B
// ---------------------------------------------------------------------------
#define SMEM_FLOATS 13616

__global__ __launch_bounds__(256, 2) void main_kernel(
    const float* __restrict__ x,
    const float* __restrict__ wc1, const float* __restrict__ g1,
    const float* __restrict__ bt1, const float* __restrict__ m1,
    const float* __restrict__ v1,
    const float* __restrict__ g2, const float* __restrict__ bt2,
    const float* __restrict__ m2, const float* __restrict__ v2,
    float* __restrict__ out)
{
    extern __shared__ float sm[];
    float* xs    = sm;
    float* f0s   = sm + 4560;
    float* weffs = sm + 13264;
    float* u1s   = sm + 13520;
    float* sh1s  = sm + 13584;
    float* sh2s  = sm + 13600;

    const int t = threadIdx.x;
    const int l0 = blockIdx.x * TL;
    const int b = blockIdx.y;

    // ---- phase A: small per-batch data into SMEM ----
    if (t < 64) {
        int c = t >> 2;
        float inv1 = g1[c] * rsqrtf(v1[c] + EPSB);
        u1s[t] = inv1 * wc1[t];
    }
    if (t < 16) {
        float inv1 = g1[t] * rsqrtf(v1[t] + EPSB);
        sh1s[t] = bt1[t] - m1[t] * inv1;
        float inv2 = g2[t] * rsqrtf(v2[t] + EPSB);
        sh2s[t] = bt2[t] - m2[t] * inv2;
    }
    weffs[t] = g_Weff[b * 256 + t];

    // ---- phase B: x tile with halo ----
    for (int idx = t; idx < 4 * XROW; idx += 256) {
        int i = idx / XROW, o = idx - i * XROW;
        int g = l0 - 32 + o;
        xs[idx] = (g >= 0 && g < LLEN) ? x[(b * 4 + i) * LLEN + g] : 0.f;
    }
    __syncthreads();

    // ---- phase C: fea0 into swizzled f0s. warp=channel d, 2 passes x 17 pos ----
    {
        const int d = t >> 5;
        const int lane = t & 31;
        const float bv = cb00[d];
        #pragma unroll
        for (int pass = 0; pass < 2; pass++) {
            const int jj0 = pass * 544 + lane * 17;
            float acc[17];
            #pragma unroll
            for (int p = 0; p < 17; p++) acc[p] = bv;
            #pragma unroll
            for (int i = 0; i < 4; i++) {
                float xw[48];
                const float* xrow = xs + i * XROW + jj0 + 2;
                #pragma unroll
                for (int m = 0; m < 48; m++) xw[m] = xrow[m];
                const float* wrow = cw00 + (d * 4 + i) * 32;
                #pragma unroll
                for (int k = 0; k < 32; k++) {
                    float wv = wrow[k];
                    #pragma unroll
                    for (int p = 0; p < 17; p++) acc[p] += wv * xw[p + k];
                }
            }
            #pragma unroll
            for (int p = 0; p < 17; p++) {
                int jj = jj0 + p;
                int j = l0 - 14 + jj;
                float val = (j >= 0 && j <= LLEN) ? acc[p] : 0.f;
                int u = jj >> 2;
                int su = u ^ ((u >> 3) & 7);
                f0s[d * FROW + su * 4 + (jj & 3)] = val;
            }
        }
    }
    __syncthreads();

    // ---- epilogue x values (kept live, 16 regs) ----
    float xgf[4][4];
    #pragma unroll
    for (int i = 0; i < 4; i++) {
        float4 v = *(const float4*)(x + (b * 4 + i) * LLEN + l0 + 4 * t);
        xgf[i][0] = v.x; xgf[i][1] = v.y; xgf[i][2] = v.z; xgf[i][3] = v.w;
    }
    const int lbase = l0 + 4 * t;

    // ================= fea1 branch: channels 0..7 =================
    {
        float acc1[4][8];
        #pragma unroll
        for (int c = 0; c < 8; c++) {
            float bA = cb01[c];
            #pragma unroll
            for (int p = 0; p < 4; p++) acc1[p][c] = bA;
        }

        #pragma unroll 1
        for (int d = 0; d < 8; d++) {
            float win1[24];   // f0[4(t+1) .. 4(t+7)-1]
            #pragma unroll
            for (int q = 0; q < 6; q++) {
                int u = t + 1 + q;
                int su = u ^ ((u >> 3) & 7);
                float4 v = *(const float4*)(f0s + d * FROW + su * 4);
                win1[4 * q] = v.x; win1[4 * q + 1] = v.y;
                win1[4 * q + 2] = v.z; win1[4 * q + 3] = v.w;
            }
            const float* wbase = cw01 + d * 16;   // [(c*8+d)*16+k] = wbase[c*128+k]
            #pragma unroll
            for (int k = 0; k < 16; k++) {
                #pragma unroll
                for (int c = 0; c < 8; c++) {
                    float wv = wbase[c * 128 + k];
                    #pragma unroll
                    for (int p = 0; p < 4; p++)
                        acc1[p][c] += wv * win1[3 + k + p];
                }
            }
        }

        // epilogue channels 0..7
        #pragma unroll
        for (int pp = 0; pp < 2; pp++) {
            float c0v[2][16];
            #pragma unroll
            for (int p2 = 0; p2 < 2; p2++) {
                int p = pp * 2 + p2;
                float x0 = xgf[0][p], x1 = xgf[1][p], x2 = xgf[2][p], x3 = xgf[3][p];
                #pragma unroll
                for (int c = 0; c < 16; c++) {
                    float4 u = *(const float4*)(u1s + c * 4);
                    float v = sh1s[c] + u.x * x0 + u.y * x1 + u.z * x2 + u.w * x3;
                    c0v[p2][c] = fmaxf(v, 0.f);
                }
            }
            const int l = lbase + 2 * pp;
            #pragma unroll
            for (int c = 0; c < 8; c++) {
                float s0 = sh2s[c], s1 = sh2s[c];
                #pragma unroll
                for (int dq = 0; dq < 16; dq += 4) {
                    float4 wv = *(const float4*)(weffs + c * 16 + dq);
                    s0 += wv.x * c0v[0][dq] + wv.y * c0v[0][dq + 1]
                        + wv.z * c0v[0][dq + 2] + wv.w * c0v[0][dq + 3];
                    s1 += wv.x * c0v[1][dq] + wv.y * c0v[1][dq + 1]
                        + wv.z * c0v[1][dq + 2] + wv.w * c0v[1][dq + 3];
                }
                *(float2*)(out + (b * 16 + c) * LLEN + l) =
                    make_float2(acc1[2 * pp][c] + fmaxf(s0, 0.f),
                                acc1[2 * pp + 1][c] + fmaxf(s1, 0.f));
            }
        }
    }

    // ================= fea2 branch: channels 8..15 =================
    {
        float acc2[4][8];
        #pragma unroll
        for (int c = 0; c < 8; c++) {
            float bB = cb02[c];
            #pragma unroll
            for (int p = 0; p < 4; p++) acc2[p][c] = bB;
        }

        #pragma unroll 1
        for (int d = 0; d < 8; d++) {
            float win2[36];   // f0[4t .. 4(t+9)-1]
            #pragma unroll
            for (int q = 0; q < 9; q++) {
                int u = t + q;
                int su = u ^ ((u >> 3) & 7);
                float4 v = *(const float4*)(f0s + d * FROW + su * 4);
                win2[4 * q] = v.x; win2[4 * q + 1] = v.y;
                win2[4 * q + 2] = v.z; win2[4 * q + 3] = v.w;
            }
            const float* wbase = cw02 + d * 16;
            #pragma unroll
            for (int k = 0; k < 16; k++) {
                #pragma unroll
                for (int c = 0; c < 8; c++) {
                    float wv = wbase[c * 128 + k];
                    #pragma unroll
                    for (int p = 0; p < 4; p++)
                        acc2[p][c] += wv * win2[2 * k + p];
                }
            }
        }

        // epilogue channels 8..15 (recompute c0v; fea2 boundary zeros)
        #pragma unroll
        for (int pp = 0; pp < 2; pp++) {
            float c0v[2][16];
            #pragma unroll
            for (int p2 = 0; p2 < 2; p2++) {
                int p = pp * 2 + p2;
                float x0 = xgf[0][p], x1 = xgf[1][p], x2 = xgf[2][p], x3 = xgf[3][p];
                #pragma unroll
                for (int c = 0; c < 16; c++) {
                    float4 u = *(const float4*)(u1s + c * 4);
                    float v = sh1s[c] + u.x * x0 + u.y * x1 + u.z * x2 + u.w * x3;
                    c0v[p2][c] = fmaxf(v, 0.f);
                }
            }
            const int l = lbase + 2 * pp;
            #pragma unroll
            for (int cc = 0; cc < 8; cc++) {
                int c = cc + 8;
                float s0 = sh2s[c], s1 = sh2s[c];
                #pragma unroll
                for (int dq = 0; dq < 16; dq += 4) {
                    float4 wv = *(const float4*)(weffs + c * 16 + dq);
                    s0 += wv.x * c0v[0][dq] + wv.y * c0v[0][dq + 1]
                        + wv.z * c0v[0][dq + 2] + wv.w * c0v[0][dq + 3];
                    s1 += wv.x * c0v[1][dq] + wv.y * c0v[1][dq + 1]
                        + wv.z * c0v[1][dq + 2] + wv.w * c0v[1][dq + 3];
                }
                float f0v = acc2[2 * pp][cc];
                float f1v = acc2[2 * pp + 1][cc];
                if (l == 0 || l >= LLEN - 2) f0v = 0.f;
                if (l + 1 >= LLEN - 2) f1v = 0.f;
                *(float2*)(out + (b * 16 + c) * LLEN + l) =
                    make_float2(f0v + fmaxf(s0, 0.f), f1v + fmaxf(s1, 0.f));
            }
        }
    }
}

// ---------------------------------------------------------------------------
extern "C" void kernel_launch(void* const* d_in, const int* in_sizes, int n_in,
                              void* d_out, int out_size)
{
    const float* x        = (const float*)d_in[0];
    const float* w00      = (const float*)d_in[1];
    const float* b00      = (const float*)d_in[2];
    const float* w01      = (const float*)d_in[3];
    const float* b01      = (const float*)d_in[4];
    const float* w02      = (const float*)d_in[5];
    const float* b02      = (const float*)d_in[6];
    const float* wc1      = (const float*)d_in[7];
    const float* g1       = (const float*)d_in[8];
    const float* bt1      = (const float*)d_in[9];
    const float* m1       = (const float*)d_in[10];
    const float* v1       = (const float*)d_in[11];
    const float* beta_cam = (const float*)d_in[12];
    const float* wc2      = (const float*)d_in[13];
    const float* g2       = (const float*)d_in[14];
    const float* bt2      = (const float*)d_in[15];
    const float* m2       = (const float*)d_in[16];
    const float* v2       = (const float*)d_in[17];
    float* out = (float*)d_out;

    cudaFuncSetAttribute(main_kernel,
                         cudaFuncAttributeMaxDynamicSharedMemorySize,
                         SMEM_FLOATS * 4);

    // D2D async copies into constant bank — graph-capturable memcpy nodes.
    cudaMemcpyToSymbolAsync(cw00, w00, 1024 * 4, 0, cudaMemcpyDeviceToDevice);
    cudaMemcpyToSymbolAsync(cw01, w01, 1024 * 4, 0, cudaMemcpyDeviceToDevice);
    cudaMemcpyToSymbolAsync(cw02, w02, 1024 * 4, 0, cudaMemcpyDeviceToDevice);
    cudaMemcpyToSymbolAsync(cb00, b00, 8 * 4, 0, cudaMemcpyDeviceToDevice);
    cudaMemcpyToSymbolAsync(cb01, b01, 8 * 4, 0, cudaMemcpyDeviceToDevice);
    cudaMemcpyToSymbolAsync(cb02, b02, 8 * 4, 0, cudaMemcpyDeviceToDevice);

    dim3 ggrid(NCHUNK, BATCH);
    gram_kernel<<<ggrid, 256>>>(x, wc1, g1, bt1, m1, v1);
    fold_kernel<<<BATCH, 256>>>(beta_cam, wc2, g2, v2);
    dim3 grid(LLEN / TL, BATCH);
    main_kernel<<<grid, 256, SMEM_FLOATS * 4>>>(
        x, wc1, g1, bt1, m1, v1, g2, bt2, m2, v2, out);
}

// round 7
// speedup vs baseline: 1.7472x; 1.1839x over previous
#include <cuda_runtime.h>
#include <math.h>

#define LLEN 8192
#define BATCH 256
#define TL 1024
#define EPSB 1e-5f
#define XROW 1140
#define FROW 1088
#define NCHUNK 8

// ---------------- device scratch ----------------
__device__ float g_gpart[NCHUNK * BATCH * 256];
__device__ float g_Weff[BATCH * 256];

// ---------------------------------------------------------------------------
// Kernel 1: partial gram of c0, 2x2 register tiling, non-atomic partials.
// Grid (NCHUNK, BATCH), 256 threads. No register hoist of weights (volatile
// SMEM reads keep regs ~70 so occupancy stays high).
// ---------------------------------------------------------------------------
__global__ __launch_bounds__(256) void gram_kernel(
    const float* __restrict__ x,
    const float* __restrict__ wc1, const float* __restrict__ g1,
    const float* __restrict__ bt1, const float* __restrict__ m1,
    const float* __restrict__ v1)
{
    __shared__ float c0s[16 * 260];
    __shared__ float u1s[64];
    __shared__ float sh1s[16];

    const int b = blockIdx.y;
    const int chunk = blockIdx.x;
    const int t = threadIdx.x;
    const int rp = t >> 5;
    const int cp = (t >> 2) & 7;
    const int ps = t & 3;

    if (t < 16) {
        float inv1 = g1[t] * rsqrtf(v1[t] + EPSB);
        sh1s[t] = bt1[t] - m1[t] * inv1;
        #pragma unroll
        for (int i = 0; i < 4; i++) u1s[t * 4 + i] = inv1 * wc1[t * 4 + i];
    }
    __syncthreads();

    // volatile: prevent ptxas from hoisting 64 weights into registers
    const volatile float* uv = u1s;
    const volatile float* sv = sh1s;

    float a00 = 0.f, a01 = 0.f, a10 = 0.f, a11 = 0.f;

    for (int ch = 0; ch < 4; ch++) {
        int p = (chunk * 4 + ch) * 256 + t;
        float xv0 = x[(b * 4 + 0) * LLEN + p];
        float xv1 = x[(b * 4 + 1) * LLEN + p];
        float xv2 = x[(b * 4 + 2) * LLEN + p];
        float xv3 = x[(b * 4 + 3) * LLEN + p];
        __syncthreads();
        #pragma unroll
        for (int c = 0; c < 16; c++) {
            float v = sv[c] + uv[c * 4 + 0] * xv0 + uv[c * 4 + 1] * xv1
                            + uv[c * 4 + 2] * xv2 + uv[c * 4 + 3] * xv3;
            c0s[c * 260 + t] = fmaxf(v, 0.f);
        }
        __syncthreads();
        const float4* r0 = (const float4*)(c0s + (2 * rp) * 260);
        const float4* r1 = (const float4*)(c0s + (2 * rp + 1) * 260);
        const float4* q0 = (const float4*)(c0s + (2 * cp) * 260);
        const float4* q1 = (const float4*)(c0s + (2 * cp + 1) * 260);
        #pragma unroll
        for (int m = 0; m < 16; m++) {
            int j = ps + 4 * m;
            float4 va0 = r0[j], va1 = r1[j];
            float4 vb0 = q0[j], vb1 = q1[j];
            a00 += va0.x * vb0.x + va0.y * vb0.y + va0.z * vb0.z + va0.w * vb0.w;
            a01 += va0.x * vb1.x + va0.y * vb1.y + va0.z * vb1.z + va0.w * vb1.w;
            a10 += va1.x * vb0.x + va1.y * vb0.y + va1.z * vb0.z + va1.w * vb0.w;
            a11 += va1.x * vb1.x + va1.y * vb1.y + va1.z * vb1.z + va1.w * vb1.w;
        }
    }

    a00 += __shfl_xor_sync(0xffffffffu, a00, 1);
    a00 += __shfl_xor_sync(0xffffffffu, a00, 2);
    a01 += __shfl_xor_sync(0xffffffffu, a01, 1);
    a01 += __shfl_xor_sync(0xffffffffu, a01, 2);
    a10 += __shfl_xor_sync(0xffffffffu, a10, 1);
    a10 += __shfl_xor_sync(0xffffffffu, a10, 2);
    a11 += __shfl_xor_sync(0xffffffffu, a11, 1);
    a11 += __shfl_xor_sync(0xffffffffu, a11, 2);

    if (ps == 0) {
        float* dst = g_gpart + (chunk * BATCH + b) * 256;
        dst[(2 * rp) * 16 + 2 * cp]         = a00;
        dst[(2 * rp) * 16 + 2 * cp + 1]     = a01;
        dst[(2 * rp + 1) * 16 + 2 * cp]     = a10;
        dst[(2 * rp + 1) * 16 + 2 * cp + 1] = a11;
    }
}

// ---------------------------------------------------------------------------
// Kernel 2: sum partials, softmax + fold into W_eff
// ---------------------------------------------------------------------------
__global__ __launch_bounds__(256) void fold_kernel(
    const float* __restrict__ beta_cam,
    const float* __restrict__ wc2, const float* __restrict__ g2,
    const float* __restrict__ v2)
{
    __shared__ float gsm[256];
    __shared__ float asmem[256];
    const int b = blockIdx.x;
    const int t = threadIdx.x;

    float s = 0.f;
    #pragma unroll
    for (int ch = 0; ch < NCHUNK; ch++)
        s += g_gpart[(ch * BATCH + b) * 256 + t];
    gsm[t] = s;
    __syncthreads();

    if (t < 16) {
        float rmin = 1e30f;
        #pragma unroll
        for (int d = 0; d < 16; d++) rmin = fminf(rmin, gsm[t * 16 + d]);
        float e[16];
        float ssum = 0.f;
        #pragma unroll
        for (int d = 0; d < 16; d++) { e[d] = expf(rmin - gsm[t * 16 + d]); ssum += e[d]; }
        float invs = 1.f / ssum;
        #pragma unroll
        for (int d = 0; d < 16; d++) asmem[t * 16 + d] = e[d] * invs;
    }
    __syncthreads();

    const int cg = t >> 4;
    const int dg = t & 15;
    float inv2c = g2[cg] * rsqrtf(v2[cg] + EPSB);
    float beta = beta_cam[0];
    float acc = 0.f;
    #pragma unroll
    for (int e = 0; e < 16; e++) acc += wc2[cg * 16 + e] * asmem[e * 16 + dg];
    g_Weff[b * 256 + t] = inv2c * (beta * acc + wc2[cg * 16 + dg]);
}

// ---------------------------------------------------------------------------
// Kernel 3: fused ConvFusion + attention epilogue.
// TL=1024, 256 threads, 4 pos/thread. SMEM weights (float4 broadcast loads),
// phase D split into two branches to bound live registers (no spills).
// SMEM (floats):
//   xs [0,4560) | f0s [4560,13264) swizzled | w00s [13264,14288)
//   w01t [14288,15312) | w02t [15312,16336) | weffs [16336,16592)
//   u1s [16592,16656) | sh1s [16656,16672) | sh2s [16672,16688)
//   b00s [16688,16696) | b01s [16696,16704) | b02s [16704,16712)
// total 16712 floats = 66848 B (2 CTA/SM = 133.7 KB)
// ---------------------------------------------------------------------------
#define SMEM_FLOATS 16712

__global__ __launch_bounds__(256, 2) void main_kernel(
    const float* __restrict__ x,
    const float* __restrict__ w00, const float* __restrict__ b00,
    const float* __restrict__ w01, const float* __restrict__ b01,
    const float* __restrict__ w02, const float* __restrict__ b02,
    const float* __restrict__ wc1, const float* __restrict__ g1,
    const float* __restrict__ bt1, const float* __restrict__ m1,
    const float* __restrict__ v1,
    const float* __restrict__ g2, const float* __restrict__ bt2,
    const float* __restrict__ m2, const float* __restrict__ v2,
    float* __restrict__ out)
{
    extern __shared__ float sm[];
    float* xs    = sm;
    float* f0s   = sm + 4560;
    float* w00s  = sm + 13264;
    float* w01t  = sm + 14288;
    float* w02t  = sm + 15312;
    float* weffs = sm + 16336;
    float* u1s   = sm + 16592;
    float* sh1s  = sm + 16656;
    float* sh2s  = sm + 16672;
    float* b00s  = sm + 16688;
    float* b01s  = sm + 16696;
    float* b02s  = sm + 16704;

    const int t = threadIdx.x;
    const int l0 = blockIdx.x * TL;
    const int b = blockIdx.y;

    // ---- phase A: weights ----
    for (int i = t; i < 1024; i += 256) {
        w00s[i] = w00[i];
        int d = i >> 7, k = (i >> 3) & 15, c = i & 7;
        w01t[i] = w01[(c * 8 + d) * 16 + k];
        w02t[i] = w02[(c * 8 + d) * 16 + k];
    }
    if (t < 64) {
        int c = t >> 2;
        float inv1 = g1[c] * rsqrtf(v1[c] + EPSB);
        u1s[t] = inv1 * wc1[t];
    }
    if (t < 16) {
        float inv1 = g1[t] * rsqrtf(v1[t] + EPSB);
        sh1s[t] = bt1[t] - m1[t] * inv1;
        float inv2 = g2[t] * rsqrtf(v2[t] + EPSB);
        sh2s[t] = bt2[t] - m2[t] * inv2;
    }
    weffs[t] = g_Weff[b * 256 + t];
    if (t < 8) { b00s[t] = b00[t]; b01s[t] = b01[t]; b02s[t] = b02[t]; }

    // ---- phase B: x tile with halo ----
    for (int idx = t; idx < 4 * XROW; idx += 256) {
        int i = idx / XROW, o = idx - i * XROW;
        int g = l0 - 32 + o;
        xs[idx] = (g >= 0 && g < LLEN) ? x[(b * 4 + i) * LLEN + g] : 0.f;
    }
    __syncthreads();

    // ---- phase C: fea0 into swizzled f0s. warp=channel d, 2 passes x 17 pos ----
    {
        const int d = t >> 5;
        const int lane = t & 31;
        const float bv = b00s[d];
        #pragma unroll
        for (int pass = 0; pass < 2; pass++) {
            const int jj0 = pass * 544 + lane * 17;
            float acc[17];
            #pragma unroll
            for (int p = 0; p < 17; p++) acc[p] = bv;
            #pragma unroll
            for (int i = 0; i < 4; i++) {
                float xw[48];
                const float* xrow = xs + i * XROW + jj0 + 2;
                #pragma unroll
                for (int m = 0; m < 48; m++) xw[m] = xrow[m];
                float wreg[32];
                const float4* wr4 = (const float4*)(w00s + (d * 4 + i) * 32);
                #pragma unroll
                for (int q = 0; q < 8; q++) {
                    float4 wv = wr4[q];
                    wreg[4 * q] = wv.x; wreg[4 * q + 1] = wv.y;
                    wreg[4 * q + 2] = wv.z; wreg[4 * q + 3] = wv.w;
                }
                #pragma unroll
                for (int k = 0; k < 32; k++) {
                    float wv = wreg[k];
                    #pragma unroll
                    for (int p = 0; p < 17; p++) acc[p] += wv * xw[p + k];
                }
            }
            #pragma unroll
            for (int p = 0; p < 17; p++) {
                int jj = jj0 + p;
                int j = l0 - 14 + jj;
                float val = (j >= 0 && j <= LLEN) ? acc[p] : 0.f;
                int u = jj >> 2;
                int su = u ^ ((u >> 3) & 7);
                f0s[d * FROW + su * 4 + (jj & 3)] = val;
            }
        }
    }
    __syncthreads();

    // ---- epilogue x values (kept live, 16 regs) ----
    float xgf[4][4];
    #pragma unroll
    for (int i = 0; i < 4; i++) {
        float4 v = *(const float4*)(x + (b * 4 + i) * LLEN + l0 + 4 * t);
        xgf[i][0] = v.x; xgf[i][1] = v.y; xgf[i][2] = v.z; xgf[i][3] = v.w;
    }
    const int lbase = l0 + 4 * t;

    // ================= fea1 branch: channels 0..7 =================
    {
        float acc1[4][8];
        #pragma unroll
        for (int c = 0; c < 8; c++) {
            float bA = b01s[c];
            #pragma unroll
            for (int p = 0; p < 4; p++) acc1[p][c] = bA;
        }

        #pragma unroll 1
        for (int d = 0; d < 8; d++) {
            float win1[24];   // f0[4(t+1) .. 4(t+7)-1]
            #pragma unroll
            for (int q = 0; q < 6; q++) {
                int u = t + 1 + q;
                int su = u ^ ((u >> 3) & 7);
                float4 v = *(const float4*)(f0s + d * FROW + su * 4);
                win1[4 * q] = v.x; win1[4 * q + 1] = v.y;
                win1[4 * q + 2] = v.z; win1[4 * q + 3] = v.w;
            }
            const float4* w1r = (const float4*)(w01t + d * 128);
            #pragma unroll
            for (int k = 0; k < 16; k++) {
                float4 a0 = w1r[2 * k], a1 = w1r[2 * k + 1];
                float wA[8] = {a0.x, a0.y, a0.z, a0.w, a1.x, a1.y, a1.z, a1.w};
                #pragma unroll
                for (int p = 0; p < 4; p++) {
                    float fA = win1[3 + k + p];
                    #pragma unroll
                    for (int c = 0; c < 8; c++)
                        acc1[p][c] += wA[c] * fA;
                }
            }
        }

        #pragma unroll
        for (int pp = 0; pp < 2; pp++) {
            float c0v[2][16];
            #pragma unroll
            for (int p2 = 0; p2 < 2; p2++) {
                int p = pp * 2 + p2;
                float x0 = xgf[0][p], x1 = xgf[1][p], x2 = xgf[2][p], x3 = xgf[3][p];
                #pragma unroll
                for (int c = 0; c < 16; c++) {
                    float4 u = *(const float4*)(u1s + c * 4);
                    float v = sh1s[c] + u.x * x0 + u.y * x1 + u.z * x2 + u.w * x3;
                    c0v[p2][c] = fmaxf(v, 0.f);
                }
            }
            const int l = lbase + 2 * pp;
            #pragma unroll
            for (int c = 0; c < 8; c++) {
                float s0 = sh2s[c], s1 = sh2s[c];
                #pragma unroll
                for (int dq = 0; dq < 16; dq += 4) {
                    float4 wv = *(const float4*)(weffs + c * 16 + dq);
                    s0 += wv.x * c0v[0][dq] + wv.y * c0v[0][dq + 1]
                        + wv.z * c0v[0][dq + 2] + wv.w * c0v[0][dq + 3];
                    s1 += wv.x * c0v[1][dq] + wv.y * c0v[1][dq + 1]
                        + wv.z * c0v[1][dq + 2] + wv.w * c0v[1][dq + 3];
                }
                *(float2*)(out + (b * 16 + c) * LLEN + l) =
                    make_float2(acc1[2 * pp][c] + fmaxf(s0, 0.f),
                                acc1[2 * pp + 1][c] + fmaxf(s1, 0.f));
            }
        }
    }

    // ================= fea2 branch: channels 8..15 =================
    {
        float acc2[4][8];
        #pragma unroll
        for (int c = 0; c < 8; c++) {
            float bB = b02s[c];
            #pragma unroll
            for (int p = 0; p < 4; p++) acc2[p][c] = bB;
        }

        #pragma unroll 1
        for (int d = 0; d < 8; d++) {
            float win2[36];   // f0[4t .. 4(t+9)-1]
            #pragma unroll
            for (int q = 0; q < 9; q++) {
                int u = t + q;
                int su = u ^ ((u >> 3) & 7);
                float4 v = *(const float4*)(f0s + d * FROW + su * 4);
                win2[4 * q] = v.x; win2[4 * q + 1] = v.y;
                win2[4 * q + 2] = v.z; win2[4 * q + 3] = v.w;
            }
            const float4* w2r = (const float4*)(w02t + d * 128);
            #pragma unroll
            for (int k = 0; k < 16; k++) {
                float4 e0 = w2r[2 * k], e1 = w2r[2 * k + 1];
                float wB[8] = {e0.x, e0.y, e0.z, e0.w, e1.x, e1.y, e1.z, e1.w};
                #pragma unroll
                for (int p = 0; p < 4; p++) {
                    float fB = win2[2 * k + p];
                    #pragma unroll
                    for (int c = 0; c < 8; c++)
                        acc2[p][c] += wB[c] * fB;
                }
            }
        }

        #pragma unroll
        for (int pp = 0; pp < 2; pp++) {
            float c0v[2][16];
            #pragma unroll
            for (int p2 = 0; p2 < 2; p2++) {
                int p = pp * 2 + p2;
                float x0 = xgf[0][p], x1 = xgf[1][p], x2 = xgf[2][p], x3 = xgf[3][p];
                #pragma unroll
                for (int c = 0; c < 16; c++) {
                    float4 u = *(const float4*)(u1s + c * 4);
                    float v = sh1s[c] + u.x * x0 + u.y * x1 + u.z * x2 + u.w * x3;
                    c0v[p2][c] = fmaxf(v, 0.f);
                }
            }
            const int l = lbase + 2 * pp;
            #pragma unroll
            for (int cc = 0; cc < 8; cc++) {
                int c = cc + 8;
                float s0 = sh2s[c], s1 = sh2s[c];
                #pragma unroll
                for (int dq = 0; dq < 16; dq += 4) {
                    float4 wv = *(const float4*)(weffs + c * 16 + dq);
                    s0 += wv.x * c0v[0][dq] + wv.y * c0v[0][dq + 1]
                        + wv.z * c0v[0][dq + 2] + wv.w * c0v[0][dq + 3];
                    s1 += wv.x * c0v[1][dq] + wv.y * c0v[1][dq + 1]
                        + wv.z * c0v[1][dq + 2] + wv.w * c0v[1][dq + 3];
                }
                float f0v = acc2[2 * pp][cc];
                float f1v = acc2[2 * pp + 1][cc];
                if (l == 0 || l >= LLEN - 2) f0v = 0.f;
                if (l + 1 >= LLEN - 2) f1v = 0.f;
                *(float2*)(out + (b * 16 + c) * LLEN + l) =
                    make_float2(f0v + fmaxf(s0, 0.f), f1v + fmaxf(s1, 0.f));
            }
        }
    }
}

// ---------------------------------------------------------------------------
extern "C" void kernel_launch(void* const* d_in, const int* in_sizes, int n_in,
                              void* d_out, int out_size)
{
    const float* x        = (const float*)d_in[0];
    const float* w00      = (const float*)d_in[1];
    const float* b00      = (const float*)d_in[2];
    const float* w01      = (const float*)d_in[3];
    const float* b01      = (const float*)d_in[4];
    const float* w02      = (const float*)d_in[5];
    const float* b02      = (const float*)d_in[6];
    const float* wc1      = (const float*)d_in[7];
    const float* g1       = (const float*)d_in[8];
    const float* bt1      = (const float*)d_in[9];
    const float* m1       = (const float*)d_in[10];
    const float* v1       = (const float*)d_in[11];
    const float* beta_cam = (const float*)d_in[12];
    const float* wc2      = (const float*)d_in[13];
    const float* g2       = (const float*)d_in[14];
    const float* bt2      = (const float*)d_in[15];
    const float* m2       = (const float*)d_in[16];
    const float* v2       = (const float*)d_in[17];
    float* out = (float*)d_out;

    cudaFuncSetAttribute(main_kernel,
                         cudaFuncAttributeMaxDynamicSharedMemorySize,
                         SMEM_FLOATS * 4);

    dim3 ggrid(NCHUNK, BATCH);
    gram_kernel<<<ggrid, 256>>>(x, wc1, g1, bt1, m1, v1);
    fold_kernel<<<BATCH, 256>>>(beta_cam, wc2, g2, v2);
    dim3 grid(LLEN / TL, BATCH);
    main_kernel<<<grid, 256, SMEM_FLOATS * 4>>>(
        x, w00, b00, w01, b01, w02, b02,
        wc1, g1, bt1, m1, v1, g2, bt2, m2, v2, out);
}